// round 15
// baseline (speedup 1.0000x reference)
#include <cuda_runtime.h>
#include <cstdint>

#define N_OSC 60
#define BDIM  128
#define NB    32        // batches per CTA (= lanes)
#define IQ    15        // i's per warp-quarter
#define STEPS 10
#define SCSTR 68        // s/c row stride (floats): phase banks 4*l, conflict-free
#define TH_STRIDE 33    // theta row stride (R11/R14-proven)

// smem floats: S[32*68] | C[32*68] | Th[60*33] | Om[64] | red[256] = 26.6 KB
#define SMEM_FLOATS (NB*SCSTR + NB*SCSTR + 60*TH_STRIDE + 64 + 256)
#define SMEM_BYTES  (SMEM_FLOATS * 4)

// raw K in constant memory: warp-uniform literal addresses -> LDCU uniform path
__constant__ float c_K[3600];

// packed f32x2 FMA (sm_103a): d = a*b + d, lanes independent
#define FMA_F32X2(d, a, b) \
    asm("fma.rn.f32x2 %0, %1, %2, %0;" : "+l"(d) : "l"(a), "l"(b))
#define UNPACK2(lo, hi, in) \
    asm("mov.b64 {%0, %1}, %2;" : "=f"(lo), "=f"(hi) : "l"(in))

__global__ __launch_bounds__(BDIM)
void kuramoto_kernel(const float* __restrict__ theta,
                     const float* __restrict__ omega,
                     const float* __restrict__ p_Kg,
                     const float* __restrict__ p_cm,
                     const float* __restrict__ p_gate,
                     const float* __restrict__ p_csf,
                     const float* __restrict__ p_ds,
                     const float* __restrict__ p_rt,
                     float* __restrict__ out,
                     int B)
{
    extern __shared__ float smem[];
    float* sS  = smem;                    // [batch][SCSTR] sin snapshot
    float* sC  = sS  + NB*SCSTR;          // [batch][SCSTR] cos snapshot
    float* sTh = sC  + NB*SCSTR;          // [i][batch], stride 33
    float* sOm = sTh + 60*TH_STRIDE;      // raw omega
    float* sRed = sOm + 64;               // reduction scratch [256]

    const int tid  = threadIdx.x;
    const int wid  = tid >> 5;            // quarter: owns i in [15*wid, 15*wid+15)
    const int lane = tid & 31;            // batch 0..31
    const int i0   = wid * IQ;
    const int bg0  = blockIdx.x * NB;

    // ---- scalar factors, emulating the reference's fp32 op order exactly ----
    const float cf     = __fdiv_rn(1.0f, __fadd_rn(1.0f, __fmul_rn(p_csf[0], p_rt[0])));
    const float eff_dt = __fmul_rn(0.1f, cf);
    const float boost  = __fadd_rn(1.0f, __fmul_rn(p_gate[0], p_ds[0]));
    const float scale  = __fdiv_rn(__fmul_rn(p_Kg[0], boost), (float)N_OSC);
    // coupling_mod folded into scale (constant holds RAW K) — R3-validated numerics
    const float scale2 = __fmul_rn(scale, p_cm[0]);

    if (tid < N_OSC) sOm[tid] = omega[tid];

    // ---- theta load: 32 batches x 15 float4, cooperative ----
    {
        const float4* th4 = (const float4*)(theta + (size_t)bg0 * N_OSC);
        #pragma unroll
        for (int l = 0; l < (NB*15)/BDIM; ++l) {
            const int idx = l * BDIM + tid;
            float4 v = th4[idx];
            const int b = idx / 15, j4 = idx % 15;
            sTh[(4*j4 + 0)*TH_STRIDE + b] = v.x;
            sTh[(4*j4 + 1)*TH_STRIDE + b] = v.y;
            sTh[(4*j4 + 2)*TH_STRIDE + b] = v.z;
            sTh[(4*j4 + 3)*TH_STRIDE + b] = v.w;
        }
        const int idx = 3 * BDIM + tid;
        if (idx < NB*15) {
            float4 v = th4[idx];
            const int b = idx / 15, j4 = idx % 15;
            sTh[(4*j4 + 0)*TH_STRIDE + b] = v.x;
            sTh[(4*j4 + 1)*TH_STRIDE + b] = v.y;
            sTh[(4*j4 + 2)*TH_STRIDE + b] = v.z;
            sTh[(4*j4 + 3)*TH_STRIDE + b] = v.w;
        }
    }
    __syncthreads();

    float* sSr = sS + lane * SCSTR;
    float* sCr = sC + lane * SCSTR;

    // ---- step-0 snapshot: warp fills j in [i0, i0+15) of batch 'lane' ----
    #pragma unroll
    for (int e = 0; e < IQ; ++e) {
        const int j = i0 + e;
        float s, c;
        __sincosf(sTh[j*TH_STRIDE + lane], &s, &c);
        sSr[j] = s;
        sCr[j] = c;
    }
    __syncthreads();

    for (int step = 0; step < STEPS; ++step) {
        // ---- packed matvec: acc halves = (sum over even j, sum over odd j) ----
        // K pairs from __constant__ (uniform literal address -> LDCU path)
        unsigned long long accS[IQ], accC[IQ];
        #pragma unroll
        for (int u = 0; u < IQ; ++u) { accS[u] = 0ull; accC[u] = 0ull; }

        #pragma unroll
        for (int j4 = 0; j4 < 15; ++j4) {
            const ulonglong2 s2 = *(const ulonglong2*)&sSr[4*j4];
            const ulonglong2 c2 = *(const ulonglong2*)&sCr[4*j4];
            #pragma unroll
            for (int u = 0; u < IQ; ++u) {
                const ulonglong2 k2 = *(const ulonglong2*)&c_K[(i0 + u)*60 + 4*j4];
                FMA_F32X2(accS[u], k2.x, s2.x);
                FMA_F32X2(accS[u], k2.y, s2.y);
                FMA_F32X2(accC[u], k2.x, c2.x);
                FMA_F32X2(accC[u], k2.y, c2.y);
            }
        }
        __syncthreads();   // all warps done reading s/c before overwrite

        // ---- epilogue: combine halves, ref-exact update + precise wrap ----
        #pragma unroll
        for (int u = 0; u < IQ; ++u) {
            const int i = i0 + u;
            float aSlo, aShi, aClo, aChi;
            UNPACK2(aSlo, aShi, accS[u]);
            UNPACK2(aClo, aChi, accC[u]);
            const float aS = aSlo + aShi;   // coupling path: reassociation tolerant
            const float aC = aClo + aChi;
            const float si = sSr[i];
            const float ci = sCr[i];
            // coupling (raw-K sums; cm folded into scale2)
            const float coupling = __fadd_rn(__fmul_rn(ci, aS),
                                             -__fmul_rn(si, aC));
            // reference op order: t = th + eff_dt*(omega + scale*coupling)
            const float tmp = __fadd_rn(sOm[i], __fmul_rn(scale2, coupling));
            const float t   = __fadd_rn(sTh[i*TH_STRIDE + lane], __fmul_rn(eff_dt, tmp));
            // reference wrap: atan2(sin t, cos t) — precise libdevice
            float sw, cw;
            sincosf(t, &sw, &cw);
            sTh[i*TH_STRIDE + lane] = atan2f(sw, cw);
            // next-step snapshot (~2e-7 vs wrapped; tolerant path)
            sSr[i] = sw;
            sCr[i] = cw;
        }
        __syncthreads();   // publish s/c + theta across warps
    }

    // ---- coherence: per-quarter partials -> smem scratch ----
    {
        float ssum = 0.f, csum = 0.f;
        #pragma unroll
        for (int e = 0; e < IQ; ++e) {
            ssum += sSr[i0 + e];
            csum += sCr[i0 + e];
        }
        sRed[wid*32 + lane]       = ssum;
        sRed[128 + wid*32 + lane] = csum;
    }
    __syncthreads();
    if (wid == 0) {
        float ssum = sRed[lane] + sRed[32 + lane] + sRed[64 + lane] + sRed[96 + lane];
        float csum = sRed[128 + lane] + sRed[160 + lane] + sRed[192 + lane] + sRed[224 + lane];
        const float sm  = __fmul_rn(ssum, 1.0f / (float)N_OSC);
        const float cm2 = __fmul_rn(csum, 1.0f / (float)N_OSC);
        out[(size_t)B * N_OSC + bg0 + lane] =
            sqrtf(__fadd_rn(__fmul_rn(cm2, cm2), __fmul_rn(sm, sm)));
    }

    // ---- theta out: cooperative float4 gather ----
    {
        float4* o4 = (float4*)(out + (size_t)bg0 * N_OSC);
        #pragma unroll
        for (int l = 0; l < (NB*15)/BDIM; ++l) {
            const int idx = l * BDIM + tid;
            const int b = idx / 15, j4 = idx % 15;
            float4 v;
            v.x = sTh[(4*j4 + 0)*TH_STRIDE + b];
            v.y = sTh[(4*j4 + 1)*TH_STRIDE + b];
            v.z = sTh[(4*j4 + 2)*TH_STRIDE + b];
            v.w = sTh[(4*j4 + 3)*TH_STRIDE + b];
            o4[idx] = v;
        }
        const int idx = 3 * BDIM + tid;
        if (idx < NB*15) {
            const int b = idx / 15, j4 = idx % 15;
            float4 v;
            v.x = sTh[(4*j4 + 0)*TH_STRIDE + b];
            v.y = sTh[(4*j4 + 1)*TH_STRIDE + b];
            v.z = sTh[(4*j4 + 2)*TH_STRIDE + b];
            v.w = sTh[(4*j4 + 3)*TH_STRIDE + b];
            o4[idx] = v;
        }
    }
}

extern "C" void kernel_launch(void* const* d_in, const int* in_sizes, int n_in,
                              void* d_out, int out_size)
{
    const float* theta = (const float*)d_in[0];
    const float* K     = (const float*)d_in[1];
    const float* omega = (const float*)d_in[2];
    const float* p_Kg   = (const float*)d_in[3];
    const float* p_cm   = (const float*)d_in[4];
    const float* p_gate = (const float*)d_in[5];
    const float* p_csf  = (const float*)d_in[6];
    const float* p_ds   = (const float*)d_in[7];
    const float* p_rt   = (const float*)d_in[8];
    float* out = (float*)d_out;

    const int B = in_sizes[0] / N_OSC;
    const int grid = B / NB;

    // raw K -> constant memory (D2D async memcpy node; graph-capturable)
    cudaMemcpyToSymbolAsync(c_K, K, 3600 * sizeof(float), 0,
                            cudaMemcpyDeviceToDevice);

    cudaFuncSetAttribute(kuramoto_kernel,
                         cudaFuncAttributeMaxDynamicSharedMemorySize, SMEM_BYTES);

    kuramoto_kernel<<<grid, BDIM, SMEM_BYTES>>>(
        theta, omega, p_Kg, p_cm, p_gate, p_csf, p_ds, p_rt, out, B);
}

// round 16
// speedup vs baseline: 5.0926x; 5.0926x over previous
#include <cuda_runtime.h>
#include <cstdint>

#define N_OSC 60
#define BDIM  128
#define NB    32        // batches per CTA (= lanes)
#define IQ    15        // i's per warp-quarter
#define STEPS 10
#define KSTR  64        // K row stride (floats): 256B, 16B-aligned rows
#define SCSTR 68        // s/c row stride (floats): 272B -> phase banks 4*l, conflict-free
#define TH_STRIDE 33    // theta row stride (R11-proven)

// smem floats: K[60*64] | S[32*68] | C[32*68] | Th[60*33] | Om[64]
#define SMEM_FLOATS (60*KSTR + NB*SCSTR + NB*SCSTR + 60*TH_STRIDE + 64)
#define SMEM_BYTES  (SMEM_FLOATS * 4)

// packed f32x2 FMA (sm_103a): d = a*b + d, lanes independent
#define FMA_F32X2(d, a, b) \
    asm("fma.rn.f32x2 %0, %1, %2, %0;" : "+l"(d) : "l"(a), "l"(b))
#define UNPACK2(lo, hi, in) \
    asm("mov.b64 {%0, %1}, %2;" : "=f"(lo), "=f"(hi) : "l"(in))

__global__ __launch_bounds__(BDIM)
void kuramoto_kernel(const float* __restrict__ theta,
                     const float* __restrict__ K,
                     const float* __restrict__ omega,
                     const float* __restrict__ p_Kg,
                     const float* __restrict__ p_cm,
                     const float* __restrict__ p_gate,
                     const float* __restrict__ p_csf,
                     const float* __restrict__ p_ds,
                     const float* __restrict__ p_rt,
                     float* __restrict__ out,
                     int B)
{
    extern __shared__ float smem[];
    float* sK  = smem;                    // K_eff [i][KSTR], rows 16B-aligned; scratch later
    float* sS  = sK  + 60*KSTR;           // [batch][SCSTR] sin snapshot
    float* sC  = sS  + NB*SCSTR;          // [batch][SCSTR] cos snapshot
    float* sTh = sC  + NB*SCSTR;          // [i][batch], stride 33
    float* sOm = sTh + 60*TH_STRIDE;      // raw omega

    const int tid  = threadIdx.x;
    const int wid  = tid >> 5;            // quarter: owns i in [15*wid, 15*wid+15)
    const int lane = tid & 31;            // batch 0..31
    const int i0   = wid * IQ;
    const int bg0  = blockIdx.x * NB;

    // ---- scalar factors, emulating the reference's fp32 op order exactly ----
    const float cf     = __fdiv_rn(1.0f, __fadd_rn(1.0f, __fmul_rn(p_csf[0], p_rt[0])));
    const float eff_dt = __fmul_rn(0.1f, cf);
    const float boost  = __fadd_rn(1.0f, __fmul_rn(p_gate[0], p_ds[0]));
    const float scale  = __fdiv_rn(__fmul_rn(p_Kg[0], boost), (float)N_OSC);

    // K_eff = K * coupling_mod (ref-exact elementwise), padded row stride 64
    {
        const float cm = p_cm[0];
        for (int idx = tid; idx < 3600; idx += BDIM) {
            const int i = idx / 60, j = idx % 60;
            sK[i*KSTR + j] = __fmul_rn(K[idx], cm);
        }
        // zero pad cols 60..63 (not read, but keep tidy)
        for (int i = tid; i < 60; i += BDIM) {
            sK[i*KSTR + 60] = 0.f; sK[i*KSTR + 61] = 0.f;
            sK[i*KSTR + 62] = 0.f; sK[i*KSTR + 63] = 0.f;
        }
    }
    if (tid < N_OSC) sOm[tid] = omega[tid];

    // ---- theta load: 32 batches x 15 float4, cooperative ----
    {
        const float4* th4 = (const float4*)(theta + (size_t)bg0 * N_OSC);
        #pragma unroll
        for (int l = 0; l < (NB*15)/BDIM; ++l) {
            const int idx = l * BDIM + tid;
            float4 v = th4[idx];
            const int b = idx / 15, j4 = idx % 15;
            sTh[(4*j4 + 0)*TH_STRIDE + b] = v.x;
            sTh[(4*j4 + 1)*TH_STRIDE + b] = v.y;
            sTh[(4*j4 + 2)*TH_STRIDE + b] = v.z;
            sTh[(4*j4 + 3)*TH_STRIDE + b] = v.w;
        }
        const int idx = 3 * BDIM + tid;
        if (idx < NB*15) {
            float4 v = th4[idx];
            const int b = idx / 15, j4 = idx % 15;
            sTh[(4*j4 + 0)*TH_STRIDE + b] = v.x;
            sTh[(4*j4 + 1)*TH_STRIDE + b] = v.y;
            sTh[(4*j4 + 2)*TH_STRIDE + b] = v.z;
            sTh[(4*j4 + 3)*TH_STRIDE + b] = v.w;
        }
    }
    __syncthreads();

    float* sSr = sS + lane * SCSTR;
    float* sCr = sC + lane * SCSTR;

    // ---- step-0 snapshot: warp fills j in [i0, i0+15) of batch 'lane' ----
    #pragma unroll
    for (int e = 0; e < IQ; ++e) {
        const int j = i0 + e;
        float s, c;
        __sincosf(sTh[j*TH_STRIDE + lane], &s, &c);
        sSr[j] = s;
        sCr[j] = c;
    }
    __syncthreads();

    for (int step = 0; step < STEPS; ++step) {
        // ---- packed matvec: acc halves = (sum over even j, sum over odd j) ----
        unsigned long long accS[IQ], accC[IQ];
        #pragma unroll
        for (int u = 0; u < IQ; ++u) { accS[u] = 0ull; accC[u] = 0ull; }

        #pragma unroll
        for (int j4 = 0; j4 < 15; ++j4) {
            // 4 j's = 2 packed pairs, straight from smem (no dup movs)
            const ulonglong2 s2 = *(const ulonglong2*)&sSr[4*j4];
            const ulonglong2 c2 = *(const ulonglong2*)&sCr[4*j4];
            #pragma unroll
            for (int u = 0; u < IQ; ++u) {
                // K pairs for this i, warp-uniform broadcast LDS.128
                const ulonglong2 k2 = *(const ulonglong2*)&sK[(i0 + u)*KSTR + 4*j4];
                FMA_F32X2(accS[u], k2.x, s2.x);
                FMA_F32X2(accS[u], k2.y, s2.y);
                FMA_F32X2(accC[u], k2.x, c2.x);
                FMA_F32X2(accC[u], k2.y, c2.y);
            }
        }
        __syncthreads();   // all warps done reading s/c before overwrite

        // ---- epilogue: combine halves, ref-exact update + precise wrap ----
        #pragma unroll
        for (int u = 0; u < IQ; ++u) {
            const int i = i0 + u;
            float aSlo, aShi, aClo, aChi;
            UNPACK2(aSlo, aShi, accS[u]);
            UNPACK2(aClo, aChi, accC[u]);
            const float aS = aSlo + aShi;   // coupling path: reassociation tolerant
            const float aC = aClo + aChi;
            const float si = sSr[i];
            const float ci = sCr[i];
            // coupling = cos_i * sum(Keff*sin) - sin_i * sum(Keff*cos)
            const float coupling = __fadd_rn(__fmul_rn(ci, aS),
                                             -__fmul_rn(si, aC));
            // reference op order: t = th + eff_dt*(omega + scale*coupling)
            const float tmp = __fadd_rn(sOm[i], __fmul_rn(scale, coupling));
            const float t   = __fadd_rn(sTh[i*TH_STRIDE + lane], __fmul_rn(eff_dt, tmp));
            // reference wrap: atan2(sin t, cos t) — precise libdevice
            float sw, cw;
            sincosf(t, &sw, &cw);
            sTh[i*TH_STRIDE + lane] = atan2f(sw, cw);
            // next-step snapshot (~2e-7 vs wrapped; tolerant path)
            sSr[i] = sw;
            sCr[i] = cw;
        }
        __syncthreads();   // publish s/c + theta across warps
    }

    // ---- coherence: per-quarter partials -> smem scratch (reuse dead sK) ----
    {
        float ssum = 0.f, csum = 0.f;
        #pragma unroll
        for (int e = 0; e < IQ; ++e) {
            ssum += sSr[i0 + e];
            csum += sCr[i0 + e];
        }
        float* redS = sK;
        float* redC = sK + 128;
        redS[wid*32 + lane] = ssum;
        redC[wid*32 + lane] = csum;
    }
    __syncthreads();
    if (wid == 0) {
        float ssum = sK[lane] + sK[32 + lane] + sK[64 + lane] + sK[96 + lane];
        float csum = sK[128 + lane] + sK[160 + lane] + sK[192 + lane] + sK[224 + lane];
        const float sm  = __fmul_rn(ssum, 1.0f / (float)N_OSC);
        const float cm2 = __fmul_rn(csum, 1.0f / (float)N_OSC);
        out[(size_t)B * N_OSC + bg0 + lane] =
            sqrtf(__fadd_rn(__fmul_rn(cm2, cm2), __fmul_rn(sm, sm)));
    }

    // ---- theta out: cooperative float4 gather ----
    {
        float4* o4 = (float4*)(out + (size_t)bg0 * N_OSC);
        #pragma unroll
        for (int l = 0; l < (NB*15)/BDIM; ++l) {
            const int idx = l * BDIM + tid;
            const int b = idx / 15, j4 = idx % 15;
            float4 v;
            v.x = sTh[(4*j4 + 0)*TH_STRIDE + b];
            v.y = sTh[(4*j4 + 1)*TH_STRIDE + b];
            v.z = sTh[(4*j4 + 2)*TH_STRIDE + b];
            v.w = sTh[(4*j4 + 3)*TH_STRIDE + b];
            o4[idx] = v;
        }
        const int idx = 3 * BDIM + tid;
        if (idx < NB*15) {
            const int b = idx / 15, j4 = idx % 15;
            float4 v;
            v.x = sTh[(4*j4 + 0)*TH_STRIDE + b];
            v.y = sTh[(4*j4 + 1)*TH_STRIDE + b];
            v.z = sTh[(4*j4 + 2)*TH_STRIDE + b];
            v.w = sTh[(4*j4 + 3)*TH_STRIDE + b];
            o4[idx] = v;
        }
    }
}

extern "C" void kernel_launch(void* const* d_in, const int* in_sizes, int n_in,
                              void* d_out, int out_size)
{
    const float* theta = (const float*)d_in[0];
    const float* K     = (const float*)d_in[1];
    const float* omega = (const float*)d_in[2];
    const float* p_Kg   = (const float*)d_in[3];
    const float* p_cm   = (const float*)d_in[4];
    const float* p_gate = (const float*)d_in[5];
    const float* p_csf  = (const float*)d_in[6];
    const float* p_ds   = (const float*)d_in[7];
    const float* p_rt   = (const float*)d_in[8];
    float* out = (float*)d_out;

    const int B = in_sizes[0] / N_OSC;
    const int grid = B / NB;

    cudaFuncSetAttribute(kuramoto_kernel,
                         cudaFuncAttributeMaxDynamicSharedMemorySize, SMEM_BYTES);

    kuramoto_kernel<<<grid, BDIM, SMEM_BYTES>>>(
        theta, K, omega, p_Kg, p_cm, p_gate, p_csf, p_ds, p_rt, out, B);
}